// round 11
// baseline (speedup 1.0000x reference)
#include <cuda_runtime.h>
#include <cuda_bf16.h>
#include <cstdint>

#define TM     128
#define KC     64
#define NCHUNK 11
#define EC     128
#define NF     656
#define NTHR   512

// smem byte offsets
#define OFF_AH    0           // 2 x 16384
#define OFF_AL    32768       // 2 x 16384
#define OFF_BH    65536       // 2 x 16384
#define OFF_BL    98304       // 2 x 16384
#define OFF_DIST  131072      // 128*41*4 = 20992
#define OFF_SMUL  152064      // 512
#define OFF_DPOS  152576      // 512
#define OFF_GAM   153088      // 512
#define OFF_BET   153600      // 512
#define SMEM_TOTAL 154112
#define OFF_OUTBUF 0          // reuse A/B region post-MMA: 128*132*4 = 67584

// Prepacked W: bf16 hi/lo, [chunk][n][kk] K-major rows of 128B, SW128-swizzled
__device__ __align__(128) __nv_bfloat16 g_Bh[NCHUNK * KC * EC];
__device__ __align__(128) __nv_bfloat16 g_Bl[NCHUNK * KC * EC];

__device__ __forceinline__ uint32_t smem_u32(const void* p) {
    return (uint32_t)__cvta_generic_to_shared(p);
}
__device__ __forceinline__ void cp_async16(uint32_t dst, const void* src) {
    asm volatile("cp.async.cg.shared.global [%0], [%1], 16;"
                 :: "r"(dst), "l"(src) : "memory");
}
__device__ __forceinline__ void ldsm4(uint32_t& r0, uint32_t& r1,
                                      uint32_t& r2, uint32_t& r3, uint32_t addr) {
    asm volatile("ldmatrix.sync.aligned.m8n8.x4.shared.b16 {%0,%1,%2,%3}, [%4];"
                 : "=r"(r0), "=r"(r1), "=r"(r2), "=r"(r3) : "r"(addr));
}
__device__ __forceinline__ void mma16816(float* d, const uint32_t* a, const uint32_t* b) {
    asm volatile("mma.sync.aligned.m16n8k16.row.col.f32.bf16.bf16.f32 "
        "{%0,%1,%2,%3}, {%4,%5,%6,%7}, {%8,%9}, {%0,%1,%2,%3};"
        : "+f"(d[0]), "+f"(d[1]), "+f"(d[2]), "+f"(d[3])
        : "r"(a[0]), "r"(a[1]), "r"(a[2]), "r"(a[3]), "r"(b[0]), "r"(b[1]));
}
__device__ __forceinline__ uint32_t sw128(uint32_t off) {
    return off ^ ((off >> 3) & 0x70);
}

// ---- prepack: W_edge -> bf16 hi/lo, swizzled, chunk-contiguous ----------
__global__ void prepack_kernel(const float* __restrict__ W_edge) {
    int idx = blockIdx.x * 256 + threadIdx.x;
    if (idx >= NCHUNK * KC * EC) return;
    int c   = idx / (KC * EC);
    int rem = idx % (KC * EC);
    int kk  = rem / EC;
    int n   = rem % EC;
    int k   = c * KC + kk;
    float v = (k < NF) ? W_edge[(size_t)k * EC + n] : 0.0f;
    __nv_bfloat16 h = __float2bfloat16(v);
    __nv_bfloat16 l = __float2bfloat16(v - __bfloat162float(h));
    uint32_t off = sw128((uint32_t)(n * 128 + kk * 2));
    *(__nv_bfloat16*)((char*)g_Bh + (size_t)c * 16384 + off) = h;
    *(__nv_bfloat16*)((char*)g_Bl + (size_t)c * 16384 + off) = l;
}

// ---- main kernel --------------------------------------------------------
__global__ __launch_bounds__(NTHR, 1)
void spf_kernel(const float* __restrict__ X,
                const int*   __restrict__ residue_idx,
                const int*   __restrict__ chain_labels,
                const int*   __restrict__ E_idx,
                const float* __restrict__ W_pos,
                const float* __restrict__ b_pos,
                const float* __restrict__ ln_gamma,
                const float* __restrict__ ln_beta,
                float*       __restrict__ out,
                int Kn, int A, int nrows, int write_eidx)
{
    extern __shared__ char smem[];
    const uint32_t sb = smem_u32(smem);
    float* dist  = (float*)(smem + OFF_DIST);
    float* smul  = (float*)(smem + OFF_SMUL);
    int*   dposs = (int*)  (smem + OFF_DPOS);
    float* sgam  = (float*)(smem + OFF_GAM);
    float* sbet  = (float*)(smem + OFF_BET);

    const int tid  = threadIdx.x;
    const int wid  = tid >> 5;
    const int lid  = tid & 31;
    const int row0 = blockIdx.x * TM;

    // staging helpers ------------------------------------------------------
    auto stage_B = [&](int c, int b) {
        const char* srcH = (const char*)g_Bh + (size_t)c * 16384;
        const char* srcL = (const char*)g_Bl + (size_t)c * 16384;
        const uint32_t dH = sb + OFF_BH + b * 16384;
        const uint32_t dL = sb + OFF_BL + b * 16384;
        #pragma unroll
        for (int i = 0; i < 2; i++) {
            int g = tid + i * NTHR;          // 0..1023
            cp_async16(dH + g*16, srcH + g*16);
            cp_async16(dL + g*16, srcL + g*16);
        }
        asm volatile("cp.async.commit_group;" ::: "memory");
    };

    auto stage_A = [&](int c, int b) {
        char* ah = smem + OFF_AH + b * 16384;
        char* al = smem + OFF_AL + b * 16384;
        const int r    = tid & 127;
        const int gsub = tid >> 7;           // 0..3
        const int gl   = c * 4 + gsub;       // global 16-k group
        float vals[16];
        if (gl == 0) {
            const int dp = dposs[r];
            #pragma unroll
            for (int m = 0; m < 16; m++)
                vals[m] = W_pos[dp*16 + m] + b_pos[m];
        } else if (gl <= 40) {
            const float d  = dist[r*41 + (gl - 1)];
            const float sm = smul[r];
            #pragma unroll
            for (int m = 0; m < 16; m++) {
                float mu = 2.0f + (float)m * (20.0f / 15.0f);
                float t  = (d - mu) * 0.8f;
                vals[m]  = sm * __expf(-t * t);
            }
        } else {
            #pragma unroll
            for (int m = 0; m < 16; m++) vals[m] = 0.0f;
        }
        uint32_t hp[8], lp[8];
        #pragma unroll
        for (int i = 0; i < 8; i++) {
            float v0 = vals[2*i], v1 = vals[2*i+1];
            __nv_bfloat162 h2 = __floats2bfloat162_rn(v0, v1);
            float l0 = v0 - __bfloat162float(h2.x);
            float l1 = v1 - __bfloat162float(h2.y);
            __nv_bfloat162 l2 = __floats2bfloat162_rn(l0, l1);
            hp[i] = *(uint32_t*)&h2;
            lp[i] = *(uint32_t*)&l2;
        }
        uint32_t base = (uint32_t)(r * 128 + gsub * 32);
        uint32_t s0 = sw128(base), s1 = sw128(base + 16);
        *(uint4*)(ah + s0) = make_uint4(hp[0], hp[1], hp[2], hp[3]);
        *(uint4*)(ah + s1) = make_uint4(hp[4], hp[5], hp[6], hp[7]);
        *(uint4*)(al + s0) = make_uint4(lp[0], lp[1], lp[2], lp[3]);
        *(uint4*)(al + s1) = make_uint4(lp[4], lp[5], lp[6], lp[7]);
    };

    // kick B chunk-0 staging immediately (independent of phase 1)
    stage_B(0, 0);

    // ---------------- Phase 1: distances, smul, dpos, gamma/beta ----------
    {
        const int r   = tid >> 2;            // 0..127
        const int a1  = tid & 3;
        const int row = row0 + r;
        if (row < nrows) {
            const int i = row / Kn;
            const int j = E_idx[row];
            const int bbm[4] = {1, 0, 2, 3};
            const float* bx = X + ((size_t)i * A + bbm[a1]) * 3;
            const float b0 = bx[0], b1 = bx[1], b2 = bx[2];
            const float* sx = X + ((size_t)j * A + 4) * 3;
            #pragma unroll
            for (int a2 = 0; a2 < 10; a2++) {
                float dx = b0 - sx[a2*3+0];
                float dy = b1 - sx[a2*3+1];
                float dz = b2 - sx[a2*3+2];
                dist[r*41 + a1*10 + a2] = sqrtf(dx*dx + dy*dy + dz*dz + 1e-6f);
            }
            if (a1 == 0) {
                smul[r] = (j == i) ? 0.0f : 1.0f;
                int off  = residue_idx[i] - residue_idx[j];
                int same = (chain_labels[i] == chain_labels[j]);
                dposs[r] = same ? min(max(off + 32, 0), 64) : 65;
                if (write_eidx)
                    out[(size_t)nrows * EC + row] = (float)j;
            }
        } else {
            #pragma unroll
            for (int a2 = 0; a2 < 10; a2++) dist[r*41 + a1*10 + a2] = 0.0f;
            if (a1 == 0) { smul[r] = 0.0f; dposs[r] = 0; }
        }
        if (tid < 128)      sgam[tid]       = ln_gamma[tid];
        else if (tid < 256) sbet[tid - 128] = ln_beta[tid - 128];
    }
    __syncthreads();

    // prologue: features for chunk 0
    stage_A(0, 0);
    asm volatile("cp.async.wait_group 0;" ::: "memory");
    __syncthreads();

    // ---------------- Phase 2: MMA mainloop -------------------------------
    // 16 warps, each owns 32 rows x 32 cols
    const int Rw = (wid & 3) * 32;
    const int Nw = (wid >> 2) * 32;
    const int q  = lid >> 3;
    const int lr = lid & 7;
    const int axor  = lr << 4;
    const int arow0 = (Rw + lr + (q & 1) * 8) * 128;   // + t*2048 per m16 tile
    const int brow0 = (Nw + lr + (q >> 1) * 8) * 128;  // + p*2048 per n16 pair
    const int akq = (q >> 1) * 16;
    const int bkq = (q & 1) * 16;

    float acc[2][4][4];
    #pragma unroll
    for (int t = 0; t < 2; t++)
        #pragma unroll
        for (int j = 0; j < 4; j++)
            #pragma unroll
            for (int e = 0; e < 4; e++) acc[t][j][e] = 0.0f;

    for (int c = 0; c < NCHUNK; c++) {
        const int b = c & 1;
        // issue next-chunk B loads FIRST: global latency hides under MMA
        if (c + 1 < NCHUNK) stage_B(c + 1, b ^ 1);

        const uint32_t aH = sb + OFF_AH + b * 16384;
        const uint32_t aL = sb + OFF_AL + b * 16384;
        const uint32_t bH = sb + OFF_BH + b * 16384;
        const uint32_t bL = sb + OFF_BL + b * 16384;

        #pragma unroll
        for (int ks = 0; ks < 4; ks++) {
            const int kb = ks * 32;
            const uint32_t aoff = (uint32_t)(arow0 + ((kb + akq) ^ axor));
            const uint32_t boff = (uint32_t)(brow0 + ((kb + bkq) ^ axor));
            uint32_t ah[2][4], al[2][4];
            ldsm4(ah[0][0], ah[0][1], ah[0][2], ah[0][3], aH + aoff);
            ldsm4(ah[1][0], ah[1][1], ah[1][2], ah[1][3], aH + aoff + 2048);
            ldsm4(al[0][0], al[0][1], al[0][2], al[0][3], aL + aoff);
            ldsm4(al[1][0], al[1][1], al[1][2], al[1][3], aL + aoff + 2048);
            #pragma unroll
            for (int p = 0; p < 2; p++) {
                uint32_t bh[4], bl[4];
                ldsm4(bh[0], bh[1], bh[2], bh[3], bH + boff + p * 2048);
                ldsm4(bl[0], bl[1], bl[2], bl[3], bL + boff + p * 2048);
                #pragma unroll
                for (int t = 0; t < 2; t++) {
                    mma16816(acc[t][2*p],   ah[t], bh);
                    mma16816(acc[t][2*p+1], ah[t], bh + 2);
                    mma16816(acc[t][2*p],   ah[t], bl);
                    mma16816(acc[t][2*p+1], ah[t], bl + 2);
                    mma16816(acc[t][2*p],   al[t], bh);
                    mma16816(acc[t][2*p+1], al[t], bh + 2);
                }
            }
        }

        // feature compute for next chunk overlaps tensor-pipe drain
        if (c + 1 < NCHUNK) stage_A(c + 1, b ^ 1);
        asm volatile("cp.async.wait_group 0;" ::: "memory");
        __syncthreads();
    }

    // ---------------- epilogue: acc -> smem, LN per row, coalesced STG ----
    float* obuf = (float*)(smem + OFF_OUTBUF);   // 128 x 132

    #pragma unroll
    for (int t = 0; t < 2; t++)
        #pragma unroll
        for (int j = 0; j < 4; j++)
            #pragma unroll
            for (int e = 0; e < 4; e++) {
                int rr = Rw + 16*t + 8*(e >> 1) + (lid >> 2);
                int cc = Nw + 8*j + (lid & 3)*2 + (e & 1);
                obuf[rr*132 + cc] = acc[t][j][e];
            }
    __syncthreads();

    // each warp: 8 rows
    const float gv0 = sgam[lid*4+0], gv1 = sgam[lid*4+1],
                gv2 = sgam[lid*4+2], gv3 = sgam[lid*4+3];
    const float bv0 = sbet[lid*4+0], bv1 = sbet[lid*4+1],
                bv2 = sbet[lid*4+2], bv3 = sbet[lid*4+3];
    #pragma unroll
    for (int ri = 0; ri < 8; ri++) {
        int rr = wid * 8 + ri;
        float4 v = *(float4*)&obuf[rr*132 + lid*4];
        float s = v.x + v.y + v.z + v.w;
        float qq = v.x*v.x + v.y*v.y + v.z*v.z + v.w*v.w;
        #pragma unroll
        for (int o = 16; o >= 1; o >>= 1) {
            s  += __shfl_xor_sync(0xffffffffu, s, o, 32);
            qq += __shfl_xor_sync(0xffffffffu, qq, o, 32);
        }
        float mean = s * (1.0f / 128.0f);
        float var  = qq * (1.0f / 128.0f) - mean * mean;
        float rstd = rsqrtf(var + 1e-5f);
        int row = row0 + rr;
        if (row < nrows) {
            float4 o4;
            o4.x = (v.x - mean) * rstd * gv0 + bv0;
            o4.y = (v.y - mean) * rstd * gv1 + bv1;
            o4.z = (v.z - mean) * rstd * gv2 + bv2;
            o4.w = (v.w - mean) * rstd * gv3 + bv3;
            *(float4*)&out[(size_t)row * EC + lid*4] = o4;
        }
    }
}

extern "C" void kernel_launch(void* const* d_in, const int* in_sizes, int n_in,
                              void* d_out, int out_size)
{
    const float* X           = (const float*)d_in[0];
    const int*   residue_idx = (const int*)  d_in[1];
    const int*   chain_lab   = (const int*)  d_in[2];
    const int*   E_idx       = (const int*)  d_in[3];
    // d_in[4] = atom_mask (unused by reference)
    const float* W_pos       = (const float*)d_in[5];
    const float* b_pos       = (const float*)d_in[6];
    const float* W_edge      = (const float*)d_in[7];
    const float* ln_gamma    = (const float*)d_in[8];
    const float* ln_beta     = (const float*)d_in[9];
    float*       out         = (float*)d_out;

    const int BL    = in_sizes[1];
    const int nrows = in_sizes[3];
    const int Kn    = nrows / BL;
    const int A     = in_sizes[0] / (BL * 3);
    const int write_eidx = (out_size >= nrows * (EC + 1)) ? 1 : 0;

    prepack_kernel<<<(NCHUNK*KC*EC + 255) / 256, 256>>>(W_edge);

    const int grid = (nrows + TM - 1) / TM;
    cudaFuncSetAttribute(spf_kernel,
                         cudaFuncAttributeMaxDynamicSharedMemorySize, SMEM_TOTAL);
    spf_kernel<<<grid, NTHR, SMEM_TOTAL>>>(X, residue_idx, chain_lab, E_idx,
                                           W_pos, b_pos, ln_gamma, ln_beta,
                                           out, Kn, A, nrows, write_eidx);
}

// round 13
// speedup vs baseline: 1.8653x; 1.8653x over previous
#include <cuda_runtime.h>
#include <cuda_fp16.h>
#include <cstdint>

#define TM     128
#define KC     64
#define NCHUNK 11
#define EC     128
#define NF     656
#define NTHR   512

// smem byte offsets (A/B double-buffered fp16 single-precision-split-free)
#define OFF_A     0           // 2 x 16384
#define OFF_B     32768       // 2 x 16384
#define OFF_DIST  69632       // 128*41*4 = 20992  (above obuf reuse region)
#define OFF_SMUL  90624       // 512
#define OFF_DPOS  91136       // 512
#define OFF_GAM   91648       // 512
#define OFF_BET   92160       // 512
#define SMEM_TOTAL 92672
#define OFF_OUTBUF 0          // reuse A/B region post-MMA: 128*132*4 = 67584

// Prepacked W: fp16, [chunk][n][kk] K-major rows of 128B, SW128-swizzled
__device__ __align__(128) __half g_B[NCHUNK * KC * EC];

__device__ __forceinline__ uint32_t smem_u32(const void* p) {
    return (uint32_t)__cvta_generic_to_shared(p);
}
__device__ __forceinline__ void cp_async16(uint32_t dst, const void* src) {
    asm volatile("cp.async.cg.shared.global [%0], [%1], 16;"
                 :: "r"(dst), "l"(src) : "memory");
}
__device__ __forceinline__ void ldsm4(uint32_t& r0, uint32_t& r1,
                                      uint32_t& r2, uint32_t& r3, uint32_t addr) {
    asm volatile("ldmatrix.sync.aligned.m8n8.x4.shared.b16 {%0,%1,%2,%3}, [%4];"
                 : "=r"(r0), "=r"(r1), "=r"(r2), "=r"(r3) : "r"(addr));
}
__device__ __forceinline__ void mma16816(float* d, const uint32_t* a, const uint32_t* b) {
    asm volatile("mma.sync.aligned.m16n8k16.row.col.f32.f16.f16.f32 "
        "{%0,%1,%2,%3}, {%4,%5,%6,%7}, {%8,%9}, {%0,%1,%2,%3};"
        : "+f"(d[0]), "+f"(d[1]), "+f"(d[2]), "+f"(d[3])
        : "r"(a[0]), "r"(a[1]), "r"(a[2]), "r"(a[3]), "r"(b[0]), "r"(b[1]));
}
__device__ __forceinline__ uint32_t sw128(uint32_t off) {
    return off ^ ((off >> 3) & 0x70);
}

// ---- prepack: W_edge -> fp16, swizzled, chunk-contiguous -----------------
__global__ void prepack_kernel(const float* __restrict__ W_edge) {
    int idx = blockIdx.x * 256 + threadIdx.x;
    if (idx >= NCHUNK * KC * EC) return;
    int c   = idx / (KC * EC);
    int rem = idx % (KC * EC);
    int kk  = rem / EC;
    int n   = rem % EC;
    int k   = c * KC + kk;
    float v = (k < NF) ? W_edge[(size_t)k * EC + n] : 0.0f;
    uint32_t off = sw128((uint32_t)(n * 128 + kk * 2));
    *(__half*)((char*)g_B + (size_t)c * 16384 + off) = __float2half(v);
}

// ---- main kernel --------------------------------------------------------
__global__ __launch_bounds__(NTHR, 1)
void spf_kernel(const float* __restrict__ X,
                const int*   __restrict__ residue_idx,
                const int*   __restrict__ chain_labels,
                const int*   __restrict__ E_idx,
                const float* __restrict__ W_pos,
                const float* __restrict__ b_pos,
                const float* __restrict__ ln_gamma,
                const float* __restrict__ ln_beta,
                float*       __restrict__ out,
                int Kn, int A, int nrows, int write_eidx)
{
    extern __shared__ char smem[];
    const uint32_t sb = smem_u32(smem);
    float* dist  = (float*)(smem + OFF_DIST);
    float* smul  = (float*)(smem + OFF_SMUL);
    int*   dposs = (int*)  (smem + OFF_DPOS);
    float* sgam  = (float*)(smem + OFF_GAM);
    float* sbet  = (float*)(smem + OFF_BET);

    const int tid  = threadIdx.x;
    const int wid  = tid >> 5;
    const int lid  = tid & 31;
    const int row0 = blockIdx.x * TM;

    // staging helpers ------------------------------------------------------
    auto stage_B = [&](int c, int b) {
        const char* src = (const char*)g_B + (size_t)c * 16384;
        const uint32_t d = sb + OFF_B + b * 16384;
        #pragma unroll
        for (int i = 0; i < 2; i++) {
            int g = tid + i * NTHR;          // 0..1023
            cp_async16(d + g*16, src + g*16);
        }
        asm volatile("cp.async.commit_group;" ::: "memory");
    };

    auto stage_A = [&](int c, int b) {
        char* ab = smem + OFF_A + b * 16384;
        const int r    = tid & 127;
        const int gsub = tid >> 7;           // 0..3
        const int gl   = c * 4 + gsub;       // global 16-k group
        float vals[16];
        if (gl == 0) {
            const int dp = dposs[r];
            #pragma unroll
            for (int m = 0; m < 16; m++)
                vals[m] = W_pos[dp*16 + m] + b_pos[m];
        } else if (gl <= 40) {
            const float d  = dist[r*41 + (gl - 1)];
            const float sm = smul[r];
            #pragma unroll
            for (int m = 0; m < 16; m++) {
                float mu = 2.0f + (float)m * (20.0f / 15.0f);
                float t  = (d - mu) * 0.8f;
                vals[m]  = sm * __expf(-t * t);
            }
        } else {
            #pragma unroll
            for (int m = 0; m < 16; m++) vals[m] = 0.0f;
        }
        uint32_t hp[8];
        #pragma unroll
        for (int i = 0; i < 8; i++) {
            __half2 h2 = __floats2half2_rn(vals[2*i], vals[2*i+1]);
            hp[i] = *(uint32_t*)&h2;
        }
        uint32_t base = (uint32_t)(r * 128 + gsub * 32);
        uint32_t s0 = sw128(base), s1 = sw128(base + 16);
        *(uint4*)(ab + s0) = make_uint4(hp[0], hp[1], hp[2], hp[3]);
        *(uint4*)(ab + s1) = make_uint4(hp[4], hp[5], hp[6], hp[7]);
    };

    // kick B chunk-0 staging immediately (independent of phase 1)
    stage_B(0, 0);

    // ---------------- Phase 1: distances, smul, dpos, gamma/beta ----------
    {
        const int r   = tid >> 2;            // 0..127
        const int a1  = tid & 3;
        const int row = row0 + r;
        if (row < nrows) {
            const int i = row / Kn;
            const int j = E_idx[row];
            const int bbm[4] = {1, 0, 2, 3};
            const float* bx = X + ((size_t)i * A + bbm[a1]) * 3;
            const float b0 = bx[0], b1 = bx[1], b2 = bx[2];
            const float* sx = X + ((size_t)j * A + 4) * 3;
            #pragma unroll
            for (int a2 = 0; a2 < 10; a2++) {
                float dx = b0 - sx[a2*3+0];
                float dy = b1 - sx[a2*3+1];
                float dz = b2 - sx[a2*3+2];
                dist[r*41 + a1*10 + a2] = sqrtf(dx*dx + dy*dy + dz*dz + 1e-6f);
            }
            if (a1 == 0) {
                smul[r] = (j == i) ? 0.0f : 1.0f;
                int off  = residue_idx[i] - residue_idx[j];
                int same = (chain_labels[i] == chain_labels[j]);
                dposs[r] = same ? min(max(off + 32, 0), 64) : 65;
                if (write_eidx)
                    out[(size_t)nrows * EC + row] = (float)j;
            }
        } else {
            #pragma unroll
            for (int a2 = 0; a2 < 10; a2++) dist[r*41 + a1*10 + a2] = 0.0f;
            if (a1 == 0) { smul[r] = 0.0f; dposs[r] = 0; }
        }
        if (tid < 128)      sgam[tid]       = ln_gamma[tid];
        else if (tid < 256) sbet[tid - 128] = ln_beta[tid - 128];
    }
    __syncthreads();

    // prologue: features for chunk 0
    stage_A(0, 0);
    asm volatile("cp.async.wait_group 0;" ::: "memory");
    __syncthreads();

    // ---------------- Phase 2: MMA mainloop (single-pass fp16) ------------
    // 16 warps, each owns 32 rows x 32 cols
    const int Rw = (wid & 3) * 32;
    const int Nw = (wid >> 2) * 32;
    const int q  = lid >> 3;
    const int lr = lid & 7;
    const int axor  = lr << 4;
    const int arow0 = (Rw + lr + (q & 1) * 8) * 128;   // + t*2048 per m16 tile
    const int brow0 = (Nw + lr + (q >> 1) * 8) * 128;  // + p*2048 per n16 pair
    const int akq = (q >> 1) * 16;
    const int bkq = (q & 1) * 16;

    float acc[2][4][4];
    #pragma unroll
    for (int t = 0; t < 2; t++)
        #pragma unroll
        for (int j = 0; j < 4; j++)
            #pragma unroll
            for (int e = 0; e < 4; e++) acc[t][j][e] = 0.0f;

    for (int c = 0; c < NCHUNK; c++) {
        const int b = c & 1;
        // issue next-chunk B loads first so global latency hides under MMA
        if (c + 1 < NCHUNK) stage_B(c + 1, b ^ 1);

        const uint32_t aB = sb + OFF_A + b * 16384;
        const uint32_t bB = sb + OFF_B + b * 16384;

        #pragma unroll
        for (int ks = 0; ks < 4; ks++) {
            const int kb = ks * 32;
            const uint32_t aoff = (uint32_t)(arow0 + ((kb + akq) ^ axor));
            const uint32_t boff = (uint32_t)(brow0 + ((kb + bkq) ^ axor));
            uint32_t ah[2][4];
            ldsm4(ah[0][0], ah[0][1], ah[0][2], ah[0][3], aB + aoff);
            ldsm4(ah[1][0], ah[1][1], ah[1][2], ah[1][3], aB + aoff + 2048);
            #pragma unroll
            for (int p = 0; p < 2; p++) {
                uint32_t bh[4];
                ldsm4(bh[0], bh[1], bh[2], bh[3], bB + boff + p * 2048);
                #pragma unroll
                for (int t = 0; t < 2; t++) {
                    mma16816(acc[t][2*p],   ah[t], bh);
                    mma16816(acc[t][2*p+1], ah[t], bh + 2);
                }
            }
        }

        // feature compute for next chunk overlaps tensor drain
        if (c + 1 < NCHUNK) stage_A(c + 1, b ^ 1);
        asm volatile("cp.async.wait_group 0;" ::: "memory");
        __syncthreads();
    }

    // ---------------- epilogue: acc -> smem, LN per row, coalesced STG ----
    float* obuf = (float*)(smem + OFF_OUTBUF);   // 128 x 132

    #pragma unroll
    for (int t = 0; t < 2; t++)
        #pragma unroll
        for (int j = 0; j < 4; j++)
            #pragma unroll
            for (int e = 0; e < 4; e++) {
                int rr = Rw + 16*t + 8*(e >> 1) + (lid >> 2);
                int cc = Nw + 8*j + (lid & 3)*2 + (e & 1);
                obuf[rr*132 + cc] = acc[t][j][e];
            }
    __syncthreads();

    // each warp: 8 rows
    const float gv0 = sgam[lid*4+0], gv1 = sgam[lid*4+1],
                gv2 = sgam[lid*4+2], gv3 = sgam[lid*4+3];
    const float bv0 = sbet[lid*4+0], bv1 = sbet[lid*4+1],
                bv2 = sbet[lid*4+2], bv3 = sbet[lid*4+3];
    #pragma unroll
    for (int ri = 0; ri < 8; ri++) {
        int rr = wid * 8 + ri;
        float4 v = *(float4*)&obuf[rr*132 + lid*4];
        float s = v.x + v.y + v.z + v.w;
        float qq = v.x*v.x + v.y*v.y + v.z*v.z + v.w*v.w;
        #pragma unroll
        for (int o = 16; o >= 1; o >>= 1) {
            s  += __shfl_xor_sync(0xffffffffu, s, o, 32);
            qq += __shfl_xor_sync(0xffffffffu, qq, o, 32);
        }
        float mean = s * (1.0f / 128.0f);
        float var  = qq * (1.0f / 128.0f) - mean * mean;
        float rstd = rsqrtf(var + 1e-5f);
        int row = row0 + rr;
        if (row < nrows) {
            float4 o4;
            o4.x = (v.x - mean) * rstd * gv0 + bv0;
            o4.y = (v.y - mean) * rstd * gv1 + bv1;
            o4.z = (v.z - mean) * rstd * gv2 + bv2;
            o4.w = (v.w - mean) * rstd * gv3 + bv3;
            *(float4*)&out[(size_t)row * EC + lid*4] = o4;
        }
    }
}

extern "C" void kernel_launch(void* const* d_in, const int* in_sizes, int n_in,
                              void* d_out, int out_size)
{
    const float* X           = (const float*)d_in[0];
    const int*   residue_idx = (const int*)  d_in[1];
    const int*   chain_lab   = (const int*)  d_in[2];
    const int*   E_idx       = (const int*)  d_in[3];
    // d_in[4] = atom_mask (unused by reference)
    const float* W_pos       = (const float*)d_in[5];
    const float* b_pos       = (const float*)d_in[6];
    const float* W_edge      = (const float*)d_in[7];
    const float* ln_gamma    = (const float*)d_in[8];
    const float* ln_beta     = (const float*)d_in[9];
    float*       out         = (float*)d_out;

    const int BL    = in_sizes[1];
    const int nrows = in_sizes[3];
    const int Kn    = nrows / BL;
    const int A     = in_sizes[0] / (BL * 3);
    const int write_eidx = (out_size >= nrows * (EC + 1)) ? 1 : 0;

    prepack_kernel<<<(NCHUNK*KC*EC + 255) / 256, 256>>>(W_edge);

    const int grid = (nrows + TM - 1) / TM;
    cudaFuncSetAttribute(spf_kernel,
                         cudaFuncAttributeMaxDynamicSharedMemorySize, SMEM_TOTAL);
    spf_kernel<<<grid, NTHR, SMEM_TOTAL>>>(X, residue_idx, chain_lab, E_idx,
                                           W_pos, b_pos, ln_gamma, ln_beta,
                                           out, Kn, A, nrows, write_eidx);
}

// round 14
// speedup vs baseline: 2.1722x; 1.1645x over previous
#include <cuda_runtime.h>
#include <cuda_fp16.h>
#include <cstdint>

#define TM     128
#define KC     64
#define NCHUNK 11
#define EC     128
#define NF     656
#define NTHR   256

// smem byte offsets
#define OFF_A     0           // 2 x 16384 (fp16 A tiles)
#define OFF_B     32768       // 2 x 16384 (fp16 B tiles)
#define OFF_DIST  69632       // 128*41*4 = 20992 (above 68KB obuf reuse region)
#define OFF_SMUL  90624       // 512
#define OFF_DPOS  91136       // 512
#define OFF_GAM   91648       // 512
#define OFF_BET   92160       // 512
#define SMEM_TOTAL 92672
#define OFF_OUTBUF 0          // reuse [0, 69632) post-MMA: 128*132*4 = 67584

// Prepacked W: fp16, [chunk][n][kk] K-major rows of 128B, SW128-swizzled
__device__ __align__(128) __half g_B[NCHUNK * KC * EC];

__device__ __forceinline__ uint32_t smem_u32(const void* p) {
    return (uint32_t)__cvta_generic_to_shared(p);
}
__device__ __forceinline__ void cp_async16(uint32_t dst, const void* src) {
    asm volatile("cp.async.cg.shared.global [%0], [%1], 16;"
                 :: "r"(dst), "l"(src) : "memory");
}
__device__ __forceinline__ void ldsm4(uint32_t& r0, uint32_t& r1,
                                      uint32_t& r2, uint32_t& r3, uint32_t addr) {
    asm volatile("ldmatrix.sync.aligned.m8n8.x4.shared.b16 {%0,%1,%2,%3}, [%4];"
                 : "=r"(r0), "=r"(r1), "=r"(r2), "=r"(r3) : "r"(addr));
}
__device__ __forceinline__ void mma16816(float* d, const uint32_t* a, const uint32_t* b) {
    asm volatile("mma.sync.aligned.m16n8k16.row.col.f32.f16.f16.f32 "
        "{%0,%1,%2,%3}, {%4,%5,%6,%7}, {%8,%9}, {%0,%1,%2,%3};"
        : "+f"(d[0]), "+f"(d[1]), "+f"(d[2]), "+f"(d[3])
        : "r"(a[0]), "r"(a[1]), "r"(a[2]), "r"(a[3]), "r"(b[0]), "r"(b[1]));
}
__device__ __forceinline__ uint32_t sw128(uint32_t off) {
    return off ^ ((off >> 3) & 0x70);
}

// ---- prepack: W_edge -> fp16, swizzled, chunk-contiguous -----------------
__global__ void prepack_kernel(const float* __restrict__ W_edge) {
    int idx = blockIdx.x * 256 + threadIdx.x;
    if (idx >= NCHUNK * KC * EC) return;
    int c   = idx / (KC * EC);
    int rem = idx % (KC * EC);
    int kk  = rem / EC;
    int n   = rem % EC;
    int k   = c * KC + kk;
    float v = (k < NF) ? W_edge[(size_t)k * EC + n] : 0.0f;
    uint32_t off = sw128((uint32_t)(n * 128 + kk * 2));
    *(__half*)((char*)g_B + (size_t)c * 16384 + off) = __float2half(v);
}

// ---- main kernel --------------------------------------------------------
__global__ __launch_bounds__(NTHR, 2)
void spf_kernel(const float* __restrict__ X,
                const int*   __restrict__ residue_idx,
                const int*   __restrict__ chain_labels,
                const int*   __restrict__ E_idx,
                const float* __restrict__ W_pos,
                const float* __restrict__ b_pos,
                const float* __restrict__ ln_gamma,
                const float* __restrict__ ln_beta,
                float*       __restrict__ out,
                int Kn, int A, int nrows, int write_eidx)
{
    extern __shared__ char smem[];
    const uint32_t sb = smem_u32(smem);
    float* dist  = (float*)(smem + OFF_DIST);
    float* smul  = (float*)(smem + OFF_SMUL);
    int*   dposs = (int*)  (smem + OFF_DPOS);
    float* sgam  = (float*)(smem + OFF_GAM);
    float* sbet  = (float*)(smem + OFF_BET);

    const int tid  = threadIdx.x;
    const int wid  = tid >> 5;
    const int lid  = tid & 31;
    const int row0 = blockIdx.x * TM;

    // staging helpers ------------------------------------------------------
    auto stage_B = [&](int c, int b) {
        const char* src = (const char*)g_B + (size_t)c * 16384;
        const uint32_t d = sb + OFF_B + b * 16384;
        #pragma unroll
        for (int i = 0; i < 4; i++) {
            int g = tid + i * NTHR;          // 0..1023
            cp_async16(d + g*16, src + g*16);
        }
        asm volatile("cp.async.commit_group;" ::: "memory");
    };

    auto stage_A = [&](int c, int b) {
        char* ab = smem + OFF_A + b * 16384;
        #pragma unroll
        for (int it = 0; it < 2; it++) {
            const int id   = tid + it * NTHR;
            const int r    = id & 127;
            const int gsub = id >> 7;        // 0..3
            const int gl   = c * 4 + gsub;   // global 16-k group
            float vals[16];
            if (gl == 0) {
                const int dp = dposs[r];
                #pragma unroll
                for (int m = 0; m < 16; m++)
                    vals[m] = W_pos[dp*16 + m] + b_pos[m];
            } else if (gl <= 40) {
                const float d  = dist[r*41 + (gl - 1)];
                const float sm = smul[r];
                #pragma unroll
                for (int m = 0; m < 16; m++) {
                    float mu = 2.0f + (float)m * (20.0f / 15.0f);
                    float t  = (d - mu) * 0.8f;
                    vals[m]  = sm * __expf(-t * t);
                }
            } else {
                #pragma unroll
                for (int m = 0; m < 16; m++) vals[m] = 0.0f;
            }
            uint32_t hp[8];
            #pragma unroll
            for (int i = 0; i < 8; i++) {
                __half2 h2 = __floats2half2_rn(vals[2*i], vals[2*i+1]);
                hp[i] = *(uint32_t*)&h2;
            }
            uint32_t base = (uint32_t)(r * 128 + gsub * 32);
            uint32_t s0 = sw128(base), s1 = sw128(base + 16);
            *(uint4*)(ab + s0) = make_uint4(hp[0], hp[1], hp[2], hp[3]);
            *(uint4*)(ab + s1) = make_uint4(hp[4], hp[5], hp[6], hp[7]);
        }
    };

    // kick B chunk-0 staging immediately (independent of phase 1)
    stage_B(0, 0);

    // ---------------- Phase 1: distances, smul, dpos, gamma/beta ----------
    {
        const int r    = tid >> 1;           // 0..127
        const int half = tid & 1;            // bb atoms {0,1} or {2,3}
        const int row  = row0 + r;
        if (row < nrows) {
            const int i = row / Kn;
            const int j = E_idx[row];
            const int bbm[4] = {1, 0, 2, 3};
            const float* sx = X + ((size_t)j * A + 4) * 3;
            float s[30];
            #pragma unroll
            for (int q = 0; q < 30; q++) s[q] = sx[q];
            #pragma unroll
            for (int aa = 0; aa < 2; aa++) {
                const int a1 = half*2 + aa;
                const float* bx = X + ((size_t)i * A + bbm[a1]) * 3;
                const float b0 = bx[0], b1 = bx[1], b2 = bx[2];
                #pragma unroll
                for (int a2 = 0; a2 < 10; a2++) {
                    float dx = b0 - s[a2*3+0];
                    float dy = b1 - s[a2*3+1];
                    float dz = b2 - s[a2*3+2];
                    dist[r*41 + a1*10 + a2] = sqrtf(dx*dx + dy*dy + dz*dz + 1e-6f);
                }
            }
            if (half == 0) {
                smul[r] = (j == i) ? 0.0f : 1.0f;
                int off  = residue_idx[i] - residue_idx[j];
                int same = (chain_labels[i] == chain_labels[j]);
                dposs[r] = same ? min(max(off + 32, 0), 64) : 65;
                if (write_eidx)
                    out[(size_t)nrows * EC + row] = (float)j;
            }
        } else {
            #pragma unroll
            for (int aa = 0; aa < 2; aa++)
                #pragma unroll
                for (int a2 = 0; a2 < 10; a2++)
                    dist[r*41 + (half*2+aa)*10 + a2] = 0.0f;
            if (half == 0) { smul[r] = 0.0f; dposs[r] = 0; }
        }
        if (tid < 128)      sgam[tid]       = ln_gamma[tid];
        else                sbet[tid - 128] = ln_beta[tid - 128];
    }
    __syncthreads();

    // prologue: features for chunk 0
    stage_A(0, 0);
    asm volatile("cp.async.wait_group 0;" ::: "memory");
    __syncthreads();

    // ---------------- Phase 2: MMA mainloop (single-pass fp16) ------------
    // 8 warps, each owns 32 rows x 64 cols
    const int Rw = (wid & 3) * 32;
    const int Nw = (wid >> 2) * 64;
    const int q  = lid >> 3;
    const int lr = lid & 7;
    const int axor  = lr << 4;
    const int arow0 = (Rw + lr + (q & 1) * 8) * 128;   // + t*2048 per m16 tile
    const int brow0 = (Nw + lr + (q >> 1) * 8) * 128;  // + p*2048 per n16 pair
    const int akq = (q >> 1) * 16;
    const int bkq = (q & 1) * 16;

    float acc[2][8][4];
    #pragma unroll
    for (int t = 0; t < 2; t++)
        #pragma unroll
        for (int j = 0; j < 8; j++)
            #pragma unroll
            for (int e = 0; e < 4; e++) acc[t][j][e] = 0.0f;

    for (int c = 0; c < NCHUNK; c++) {
        const int b = c & 1;
        // issue next-chunk B loads first so global latency hides under MMA
        if (c + 1 < NCHUNK) stage_B(c + 1, b ^ 1);

        const uint32_t aB = sb + OFF_A + b * 16384;
        const uint32_t bB = sb + OFF_B + b * 16384;

        #pragma unroll
        for (int ks = 0; ks < 4; ks++) {
            const int kb = ks * 32;
            const uint32_t aoff = (uint32_t)(arow0 + ((kb + akq) ^ axor));
            const uint32_t boff = (uint32_t)(brow0 + ((kb + bkq) ^ axor));
            uint32_t ah[2][4];
            ldsm4(ah[0][0], ah[0][1], ah[0][2], ah[0][3], aB + aoff);
            ldsm4(ah[1][0], ah[1][1], ah[1][2], ah[1][3], aB + aoff + 2048);
            #pragma unroll
            for (int p = 0; p < 4; p++) {
                uint32_t bh[4];
                ldsm4(bh[0], bh[1], bh[2], bh[3], bB + boff + p * 2048);
                #pragma unroll
                for (int t = 0; t < 2; t++) {
                    mma16816(acc[t][2*p],   ah[t], bh);
                    mma16816(acc[t][2*p+1], ah[t], bh + 2);
                }
            }
        }

        // feature compute for next chunk overlaps tensor drain
        if (c + 1 < NCHUNK) stage_A(c + 1, b ^ 1);
        asm volatile("cp.async.wait_group 0;" ::: "memory");
        __syncthreads();
    }

    // ---------------- epilogue: acc -> smem, LN per row, coalesced STG ----
    float* obuf = (float*)(smem + OFF_OUTBUF);   // 128 x 132

    #pragma unroll
    for (int t = 0; t < 2; t++)
        #pragma unroll
        for (int j = 0; j < 8; j++)
            #pragma unroll
            for (int e = 0; e < 4; e++) {
                int rr = Rw + 16*t + 8*(e >> 1) + (lid >> 2);
                int cc = Nw + 8*j + (lid & 3)*2 + (e & 1);
                obuf[rr*132 + cc] = acc[t][j][e];
            }
    __syncthreads();

    // each warp: 16 rows
    const float gv0 = sgam[lid*4+0], gv1 = sgam[lid*4+1],
                gv2 = sgam[lid*4+2], gv3 = sgam[lid*4+3];
    const float bv0 = sbet[lid*4+0], bv1 = sbet[lid*4+1],
                bv2 = sbet[lid*4+2], bv3 = sbet[lid*4+3];
    #pragma unroll
    for (int ri = 0; ri < 16; ri++) {
        int rr = wid * 16 + ri;
        float4 v = *(float4*)&obuf[rr*132 + lid*4];
        float s = v.x + v.y + v.z + v.w;
        float qq = v.x*v.x + v.y*v.y + v.z*v.z + v.w*v.w;
        #pragma unroll
        for (int o = 16; o >= 1; o >>= 1) {
            s  += __shfl_xor_sync(0xffffffffu, s, o, 32);
            qq += __shfl_xor_sync(0xffffffffu, qq, o, 32);
        }
        float mean = s * (1.0f / 128.0f);
        float var  = qq * (1.0f / 128.0f) - mean * mean;
        float rstd = rsqrtf(var + 1e-5f);
        int row = row0 + rr;
        if (row < nrows) {
            float4 o4;
            o4.x = (v.x - mean) * rstd * gv0 + bv0;
            o4.y = (v.y - mean) * rstd * gv1 + bv1;
            o4.z = (v.z - mean) * rstd * gv2 + bv2;
            o4.w = (v.w - mean) * rstd * gv3 + bv3;
            *(float4*)&out[(size_t)row * EC + lid*4] = o4;
        }
    }
}

extern "C" void kernel_launch(void* const* d_in, const int* in_sizes, int n_in,
                              void* d_out, int out_size)
{
    const float* X           = (const float*)d_in[0];
    const int*   residue_idx = (const int*)  d_in[1];
    const int*   chain_lab   = (const int*)  d_in[2];
    const int*   E_idx       = (const int*)  d_in[3];
    // d_in[4] = atom_mask (unused by reference)
    const float* W_pos       = (const float*)d_in[5];
    const float* b_pos       = (const float*)d_in[6];
    const float* W_edge      = (const float*)d_in[7];
    const float* ln_gamma    = (const float*)d_in[8];
    const float* ln_beta     = (const float*)d_in[9];
    float*       out         = (float*)d_out;

    const int BL    = in_sizes[1];
    const int nrows = in_sizes[3];
    const int Kn    = nrows / BL;
    const int A     = in_sizes[0] / (BL * 3);
    const int write_eidx = (out_size >= nrows * (EC + 1)) ? 1 : 0;

    prepack_kernel<<<(NCHUNK*KC*EC + 255) / 256, 256>>>(W_edge);

    const int grid = (nrows + TM - 1) / TM;
    cudaFuncSetAttribute(spf_kernel,
                         cudaFuncAttributeMaxDynamicSharedMemorySize, SMEM_TOTAL);
    spf_kernel<<<grid, NTHR, SMEM_TOTAL>>>(X, residue_idx, chain_lab, E_idx,
                                           W_pos, b_pos, ln_gamma, ln_beta,
                                           out, Kn, A, nrows, write_eidx);
}